// round 7
// baseline (speedup 1.0000x reference)
#include <cuda_runtime.h>
#include <cuda_bf16.h>
#include <cstdint>

// PositionalEncoding2D — TMA-store experiment.
//   pe[i,b,2p] = sin(x0*dt[p]), pe[i,b,2p+1] = cos(x1*dt[p]), dt[p]=exp(p*-ln(1e4)/256)
// Output 128 MB fp32, pure store-bandwidth problem. R6 showed STG.128 path
// reaches ~6.6 TB/s into L2 (= measured LTS cap @LOCK). This version drains
// through TMA bulk stores (SMEM -> GMEM, bypassing the L1tex store pipeline)
// to test whether the store-side cap is path-independent at NAT clocks.
//
// Structure: 2048 CTAs x 256 threads. CTA covers 32 rows = 4 tiles of 8 rows.
// Per tile: warp w computes row w (lane covers quads l, l+32, l+64, l+96)
// into a 16 KB SMEM buffer; one thread issues cp.async.bulk (16 KB) to GMEM.
// Double-buffered: compute of tile t+1 overlaps bulk store of tile t.

#define NUM_ROWS (2048 * 32)   // 65536

__device__ __forceinline__ uint32_t smem_u32(const void* p) {
    uint32_t a;
    asm("{ .reg .u64 t; cvta.to.shared.u64 t, %1; cvt.u32.u64 %0, t; }"
        : "=r"(a) : "l"(p));
    return a;
}

__global__ __launch_bounds__(256)
void pe2d_kernel(const float* __restrict__ x, float4* __restrict__ out) {
    __shared__ float4 buf[2][8][128];   // 2 x 16 KB

    const int tid  = threadIdx.x;
    const int w    = tid >> 5;
    const int lane = tid & 31;
    const int cta_row0 = blockIdx.x * 32;

    // dt for quad t: exp(2t*C), C = -ln(1e4)/256; +32 quads multiplies by 0.1
    const float twoC = -9.210340371976184f / 128.0f;
    const float r    = 0.9646616199111993f;          // pair step 1e4^(-1/256)
    const float d0 = __expf((float)lane * twoC);
    const float d1 = d0 * 0.1f, d2 = d1 * 0.1f, d3 = d2 * 0.1f;
    const float e0 = d0 * r, e1 = d1 * r, e2 = d2 * r, e3 = d3 * r;

    #pragma unroll
    for (int t = 0; t < 4; t++) {
        const int p = t & 1;
        if (t >= 2) {
            // buf[p] was handed to TMA 2 iterations ago; wait until its read
            // is done (allow the newest 1 group to remain in flight).
            if (tid == 0)
                asm volatile("cp.async.bulk.wait_group.read 1;" ::: "memory");
            __syncthreads();
        }

        const int row = cta_row0 + t * 8 + w;
        const float2 xy = __ldg(reinterpret_cast<const float2*>(x) + row);

        float4 a;
        a.x = __sinf(xy.x * d0); a.y = __cosf(xy.y * d0);
        a.z = __sinf(xy.x * e0); a.w = __cosf(xy.y * e0);
        buf[p][w][lane] = a;
        a.x = __sinf(xy.x * d1); a.y = __cosf(xy.y * d1);
        a.z = __sinf(xy.x * e1); a.w = __cosf(xy.y * e1);
        buf[p][w][lane + 32] = a;
        a.x = __sinf(xy.x * d2); a.y = __cosf(xy.y * d2);
        a.z = __sinf(xy.x * e2); a.w = __cosf(xy.y * e2);
        buf[p][w][lane + 64] = a;
        a.x = __sinf(xy.x * d3); a.y = __cosf(xy.y * d3);
        a.z = __sinf(xy.x * e3); a.w = __cosf(xy.y * e3);
        buf[p][w][lane + 96] = a;

        __syncthreads();

        if (tid == 0) {
            asm volatile("fence.proxy.async.shared::cta;" ::: "memory");
            uint32_t s = smem_u32(&buf[p][0][0]);
            void* g = (void*)(out + (size_t)(cta_row0 + t * 8) * 128);
            asm volatile(
                "cp.async.bulk.global.shared::cta.bulk_group [%0], [%1], %2;"
                :: "l"(g), "r"(s), "r"(16384u) : "memory");
            asm volatile("cp.async.bulk.commit_group;" ::: "memory");
        }
    }

    // Ensure all bulk stores are fully complete before CTA exit.
    if (tid == 0)
        asm volatile("cp.async.bulk.wait_group 0;" ::: "memory");
}

extern "C" void kernel_launch(void* const* d_in, const int* in_sizes, int n_in,
                              void* d_out, int out_size) {
    const float* x = (const float*)d_in[0];
    float4* out = (float4*)d_out;
    pe2d_kernel<<<NUM_ROWS / 32, 256>>>(x, out);   // 2048 CTAs
}

// round 8
// speedup vs baseline: 1.0285x; 1.0285x over previous
#include <cuda_runtime.h>
#include <cuda_bf16.h>
#include <cstdint>

// PositionalEncoding2D:
//   pe[i,b,2j]   = sin(x[i,b,0] * dt[j])
//   pe[i,b,2j+1] = cos(x[i,b,1] * dt[j]),  dt[j] = exp(j * -ln(1e4)/256), j in [0,256)
//
// Output 128 MB fp32 — store-bandwidth bound at the LTS cap (~6.6 TB/s, path-
// independent per R6/R7 STG-vs-TMA experiment). This round: Blackwell 256-bit
// stores (st.global.v8.f32 -> STG.256) to halve per-SM store-issue cost.
//
// Layout: one warp = 2 rows. Lane l owns 32-byte chunks {l, l+32} of each row
// (chunk c = pairs 4c..4c+3). dt recurrence: pair step r = 1e4^(-1/256),
// chunk step +32 multiplies dt by exp(128C) = 0.01 exactly.

#define NUM_ROWS (2048 * 32)   // 65536

__device__ __forceinline__ void stg256(float* p, const float v[8]) {
    asm volatile(
        "st.global.v8.f32 [%0], {%1,%2,%3,%4,%5,%6,%7,%8};"
        :: "l"(p), "f"(v[0]), "f"(v[1]), "f"(v[2]), "f"(v[3]),
                   "f"(v[4]), "f"(v[5]), "f"(v[6]), "f"(v[7])
        : "memory");
}

__global__ __launch_bounds__(256)
void pe2d_kernel(const float4* __restrict__ x, float* __restrict__ out) {
    const int warp = (blockIdx.x * 256 + threadIdx.x) >> 5;  // row-pair index
    const int lane = threadIdx.x & 31;

    // Coords for rows 2w, 2w+1 (uniform within warp)
    const float4 xy2 = __ldg(x + warp);

    // dt at pair j = 4*lane
    const float C  = -9.210340371976184f / 256.0f;
    const float r  = 0.9646616199111993f;          // exp(C)
    const float r2 = r * r, r3 = r2 * r;
    const float dA0 = __expf((float)(lane << 2) * C);      // chunk lane
    const float dA1 = dA0 * r, dA2 = dA0 * r2, dA3 = dA0 * r3;
    const float dB0 = dA0 * 0.01f;                          // chunk lane+32
    const float dB1 = dB0 * r, dB2 = dB0 * r2, dB3 = dB0 * r3;

    float* o = out + (size_t)warp * 1024 + (lane << 3);

    float v[8];
    // row 0, chunk lane
    v[0] = __sinf(xy2.x * dA0); v[1] = __cosf(xy2.y * dA0);
    v[2] = __sinf(xy2.x * dA1); v[3] = __cosf(xy2.y * dA1);
    v[4] = __sinf(xy2.x * dA2); v[5] = __cosf(xy2.y * dA2);
    v[6] = __sinf(xy2.x * dA3); v[7] = __cosf(xy2.y * dA3);
    stg256(o, v);
    // row 0, chunk lane+32
    v[0] = __sinf(xy2.x * dB0); v[1] = __cosf(xy2.y * dB0);
    v[2] = __sinf(xy2.x * dB1); v[3] = __cosf(xy2.y * dB1);
    v[4] = __sinf(xy2.x * dB2); v[5] = __cosf(xy2.y * dB2);
    v[6] = __sinf(xy2.x * dB3); v[7] = __cosf(xy2.y * dB3);
    stg256(o + 256, v);
    // row 1, chunk lane
    v[0] = __sinf(xy2.z * dA0); v[1] = __cosf(xy2.w * dA0);
    v[2] = __sinf(xy2.z * dA1); v[3] = __cosf(xy2.w * dA1);
    v[4] = __sinf(xy2.z * dA2); v[5] = __cosf(xy2.w * dA2);
    v[6] = __sinf(xy2.z * dA3); v[7] = __cosf(xy2.w * dA3);
    stg256(o + 512, v);
    // row 1, chunk lane+32
    v[0] = __sinf(xy2.z * dB0); v[1] = __cosf(xy2.w * dB0);
    v[2] = __sinf(xy2.z * dB1); v[3] = __cosf(xy2.w * dB1);
    v[4] = __sinf(xy2.z * dB2); v[5] = __cosf(xy2.w * dB2);
    v[6] = __sinf(xy2.z * dB3); v[7] = __cosf(xy2.w * dB3);
    stg256(o + 768, v);
}

extern "C" void kernel_launch(void* const* d_in, const int* in_sizes, int n_in,
                              void* d_out, int out_size) {
    const float4* x = (const float4*)d_in[0];
    float* out = (float*)d_out;
    // 65536 rows, 2 rows/warp, 8 warps/block -> 4096 blocks
    pe2d_kernel<<<NUM_ROWS / 16, 256>>>(x, out);
}